// round 4
// baseline (speedup 1.0000x reference)
#include <cuda_runtime.h>
#include <cstdint>

// Problem constants (fixed by the reference)
#define N_NODES 50000
#define N_EDGES 800000
#define FDIM    128
#define HDIM    128
#define TDIM    10

// Scratch (device globals; 16B alignment for float4 access)
__device__ __align__(16) float g_dinv[N_NODES];
__device__ __align__(16) float g_norm[N_EDGES];
__device__ __align__(16) float g_T1[N_NODES * FDIM];
__device__ __align__(16) float g_T2[N_NODES * FDIM];  // prop(T1), then 2*prop(T1)-x

// ---------------------------------------------------------------------------
// Stage 0: zero scratch
// ---------------------------------------------------------------------------
__global__ void zero_kernel() {
    int i = blockIdx.x * blockDim.x + threadIdx.x;
    const int n4 = N_NODES * FDIM / 4;
    if (i < n4) {
        ((float4*)g_T1)[i] = make_float4(0.f, 0.f, 0.f, 0.f);
        ((float4*)g_T2)[i] = make_float4(0.f, 0.f, 0.f, 0.f);
    }
    if (i < N_NODES) g_dinv[i] = 0.f;
}

// ---------------------------------------------------------------------------
// Stage 1: degree = segment_sum(edge_weight, src)   (edge_index is INT32)
// ---------------------------------------------------------------------------
__global__ void deg_kernel(const int* __restrict__ ei,
                           const float* __restrict__ ew) {
    int e = blockIdx.x * blockDim.x + threadIdx.x;
    if (e < N_EDGES) {
        atomicAdd(&g_dinv[ei[e]], ew[e]);
    }
}

// Stage 2: dinv = deg > 0 ? rsqrt(deg) : 0   (in place)
__global__ void dinv_kernel() {
    int n = blockIdx.x * blockDim.x + threadIdx.x;
    if (n < N_NODES) {
        float d = g_dinv[n];
        g_dinv[n] = (d > 0.f) ? rsqrtf(d) : 0.f;
    }
}

// Stage 3: norm[e] = -dinv[src] * w[e] * dinv[dst]
__global__ void norm_kernel(const int* __restrict__ ei,
                            const float* __restrict__ ew) {
    int e = blockIdx.x * blockDim.x + threadIdx.x;
    if (e < N_EDGES) {
        int s = ei[e];
        int d = ei[N_EDGES + e];
        g_norm[e] = -g_dinv[s] * ew[e] * g_dinv[d];
    }
}

// ---------------------------------------------------------------------------
// Stage 4/5: propagation  out[dst] += norm * in[src]   (one warp per edge)
// Each lane: one float4 gather + 4 scalar REDG.ADD.F32.
// ---------------------------------------------------------------------------
__device__ __forceinline__ void prop_body(const int* __restrict__ ei,
                                          const float* __restrict__ in,
                                          float* __restrict__ out) {
    int gw   = (blockIdx.x * blockDim.x + threadIdx.x) >> 5;
    int lane = threadIdx.x & 31;
    if (gw >= N_EDGES) return;
    float nrm = g_norm[gw];
    if (nrm == 0.f) return;
    int s = ei[gw];
    int d = ei[N_EDGES + gw];
    float4 v = ((const float4*)(in + (size_t)s * FDIM))[lane];
    float* dst = out + (size_t)d * FDIM + lane * 4;
    atomicAdd(dst + 0, v.x * nrm);
    atomicAdd(dst + 1, v.y * nrm);
    atomicAdd(dst + 2, v.z * nrm);
    atomicAdd(dst + 3, v.w * nrm);
}

__global__ void prop1_kernel(const int* __restrict__ ei,
                             const float* __restrict__ x) {
    prop_body(ei, x, g_T1);
}

__global__ void prop2_kernel(const int* __restrict__ ei) {
    prop_body(ei, g_T1, g_T2);
}

// Stage 6: T2 = 2 * prop(T1) - x
__global__ void finalize_kernel(const float* __restrict__ x) {
    int i = blockIdx.x * blockDim.x + threadIdx.x;
    const int n4 = N_NODES * FDIM / 4;
    if (i < n4) {
        float4 p  = ((float4*)g_T2)[i];
        float4 xx = ((const float4*)x)[i];
        p.x = 2.f * p.x - xx.x;
        p.y = 2.f * p.y - xx.y;
        p.z = 2.f * p.z - xx.z;
        p.w = 2.f * p.w - xx.w;
        ((float4*)g_T2)[i] = p;
    }
}

// ---------------------------------------------------------------------------
// Stage 7: fused GEMM + gate epilogue + output projection
//   A (virtual) = [x | T1 | T2]  : 50000 x 384
//   zpre = A@Wz + bxz + bhz ; hpre = A@Wh + bxh + bhh
//   Hn = (1 - sigmoid(zpre)) * tanh(hpre) ;  out = Hn @ Wlin + blin
// ---------------------------------------------------------------------------
#define BM  64
#define BK  32
#define NKB 12                          // 384 / 32
#define STAGE_FLOATS (BM*BK + BK*256)   // 2048 + 8192 = 10240

extern __shared__ float smem[];

__device__ __forceinline__ void cp_async16(uint32_t saddr, const float* g, int bytes) {
    asm volatile("cp.async.cg.shared.global [%0], [%1], 16, %2;"
                 :: "r"(saddr), "l"(g), "r"(bytes) : "memory");
}

__global__ __launch_bounds__(256, 2) void fused_kernel(
    const float* __restrict__ x,
    const float* __restrict__ Wz, const float* __restrict__ Wh,
    const float* __restrict__ bz0, const float* __restrict__ bz1,
    const float* __restrict__ bh0, const float* __restrict__ bh1,
    const float* __restrict__ Wlin, const float* __restrict__ blin,
    float* __restrict__ out)
{
    const int tid = threadIdx.x;
    const int tx  = tid & 15;
    const int ty  = tid >> 4;
    const int m0  = blockIdx.x * BM;

    const uint32_t smem_u32 = (uint32_t)__cvta_generic_to_shared(smem);

    float cz[4][8];
    float ch[4][8];
#pragma unroll
    for (int r = 0; r < 4; r++)
#pragma unroll
        for (int i = 0; i < 8; i++) { cz[r][i] = 0.f; ch[r][i] = 0.f; }

    auto load_stage = [&](int kb, int s) {
        const int col = kb * BK;
        const float* Asrc;
        int c0;
        if (col < 128)      { Asrc = x;    c0 = col; }
        else if (col < 256) { Asrc = g_T1; c0 = col - 128; }
        else                { Asrc = g_T2; c0 = col - 256; }

        uint32_t sa = smem_u32 + (uint32_t)(s * STAGE_FLOATS) * 4u;
        uint32_t sb = sa + BM * BK * 4u;

#pragma unroll
        for (int j = 0; j < 2; j++) {
            int idx = tid + j * 256;
            int m = idx >> 3;
            int c = idx & 7;
            int node  = m0 + m;
            int bytes = (node < N_NODES) ? 16 : 0;
            int nd    = (node < N_NODES) ? node : 0;
            cp_async16(sa + (uint32_t)(m * BK + c * 4) * 4u,
                       Asrc + (size_t)nd * FDIM + c0 + c * 4, bytes);
        }
#pragma unroll
        for (int j = 0; j < 8; j++) {
            int idx  = tid + j * 256;
            int jr   = idx >> 6;
            int col4 = (idx & 63) * 4;
            const float* src = (col4 < 128)
                ? (Wz + (size_t)(col + jr) * 128 + col4)
                : (Wh + (size_t)(col + jr) * 128 + (col4 - 128));
            cp_async16(sb + (uint32_t)(jr * 256 + col4) * 4u, src, 16);
        }
        asm volatile("cp.async.commit_group;" ::: "memory");
    };

    load_stage(0, 0);

    for (int kb = 0; kb < NKB; kb++) {
        int s = kb & 1;
        if (kb + 1 < NKB) {
            load_stage(kb + 1, s ^ 1);
            asm volatile("cp.async.wait_group 1;" ::: "memory");
        } else {
            asm volatile("cp.async.wait_group 0;" ::: "memory");
        }
        __syncthreads();

        const float* A = smem + s * STAGE_FLOATS;
        const float* B = A + BM * BK;

#pragma unroll
        for (int k = 0; k < BK; k++) {
            float a[4];
#pragma unroll
            for (int r = 0; r < 4; r++) a[r] = A[(ty * 4 + r) * BK + k];

            float4 z0 = *(const float4*)(B + k * 256 + tx * 8);
            float4 z1 = *(const float4*)(B + k * 256 + tx * 8 + 4);
            float4 h0 = *(const float4*)(B + k * 256 + 128 + tx * 8);
            float4 h1 = *(const float4*)(B + k * 256 + 128 + tx * 8 + 4);
            float bz[8] = {z0.x, z0.y, z0.z, z0.w, z1.x, z1.y, z1.z, z1.w};
            float bh[8] = {h0.x, h0.y, h0.z, h0.w, h1.x, h1.y, h1.z, h1.w};
#pragma unroll
            for (int r = 0; r < 4; r++) {
#pragma unroll
                for (int i = 0; i < 8; i++) {
                    cz[r][i] += a[r] * bz[i];
                    ch[r][i] += a[r] * bh[i];
                }
            }
        }
        __syncthreads();
    }

    // ---- gate epilogue: Hn into smem ----
    float* Hs = smem;            // [BM][130]
#pragma unroll
    for (int i = 0; i < 8; i++) {
        int h = tx * 8 + i;
        float bzs = bz0[h] + bz1[h];
        float bhs = bh0[h] + bh1[h];
#pragma unroll
        for (int r = 0; r < 4; r++) {
            int m = ty * 4 + r;
            float z  = cz[r][i] + bzs;
            float hp = ch[r][i] + bhs;
            float sig = 1.f / (1.f + __expf(-z));
            Hs[m * 130 + h] = (1.f - sig) * tanhf(hp);
        }
    }
    __syncthreads();

    // ---- output projection ----
    for (int idx = tid; idx < BM * TDIM; idx += 256) {
        int m = idx / TDIM;
        int t = idx % TDIM;
        int node = m0 + m;
        if (node < N_NODES) {
            float acc = blin[t];
            const float* hrow = Hs + m * 130;
#pragma unroll 16
            for (int h = 0; h < HDIM; h++)
                acc += hrow[h] * Wlin[h * TDIM + t];
            out[(size_t)node * TDIM + t] = acc;
        }
    }
}

// ---------------------------------------------------------------------------
// Launch
// ---------------------------------------------------------------------------
extern "C" void kernel_launch(void* const* d_in, const int* in_sizes, int n_in,
                              void* d_out, int out_size) {
    const float* x    = (const float*)d_in[0];
    const int*   ei   = (const int*)d_in[1];      // int32! (JAX x64 disabled)
    const float* ew   = (const float*)d_in[2];
    const float* Wxz  = (const float*)d_in[3];
    const float* bxz  = (const float*)d_in[4];
    const float* bhz  = (const float*)d_in[6];
    const float* Wxh  = (const float*)d_in[11];
    const float* bxh  = (const float*)d_in[12];
    const float* bhh  = (const float*)d_in[14];
    const float* Wlin = (const float*)d_in[15];
    const float* blin = (const float*)d_in[16];
    float*       out  = (float*)d_out;

    const int smem_bytes = 2 * STAGE_FLOATS * sizeof(float);   // 81920
    cudaFuncSetAttribute(fused_kernel,
                         cudaFuncAttributeMaxDynamicSharedMemorySize, smem_bytes);

    const int n4 = N_NODES * FDIM / 4;
    zero_kernel<<<(n4 + 255) / 256, 256>>>();
    deg_kernel<<<(N_EDGES + 255) / 256, 256>>>(ei, ew);
    dinv_kernel<<<(N_NODES + 255) / 256, 256>>>();
    norm_kernel<<<(N_EDGES + 255) / 256, 256>>>(ei, ew);

    prop1_kernel<<<(N_EDGES * 32) / 256, 256>>>(ei, x);
    prop2_kernel<<<(N_EDGES * 32) / 256, 256>>>(ei);
    finalize_kernel<<<(n4 + 255) / 256, 256>>>(x);

    fused_kernel<<<(N_NODES + BM - 1) / BM, 256, smem_bytes>>>(
        x, Wxz, Wxh, bxz, bhz, bxh, bhh, Wlin, blin, out);
}

// round 7
// speedup vs baseline: 1.5296x; 1.5296x over previous
#include <cuda_runtime.h>
#include <cstdint>

#define N_NODES 50000
#define N_EDGES 800000
#define FDIM    128
#define HDIM    128
#define TDIM    10

// Scratch (device globals) — only ever referenced from DEVICE code.
__device__ __align__(16) float g_dinv[N_NODES];
__device__ __align__(16) float g_norm[N_EDGES];
__device__ int  g_cnt[N_NODES];
__device__ int  g_rowptr[N_NODES];
__device__ int  g_cursor[N_NODES];
__device__ __align__(16) int2  g_edges[N_EDGES];   // (src, norm bits), grouped by dst
__device__ __align__(16) float g_T1[N_NODES * FDIM];
__device__ __align__(16) float g_T2[N_NODES * FDIM];

// ---------------------------------------------------------------------------
// Stage 0: zero degree / per-dst count
// ---------------------------------------------------------------------------
__global__ void init_kernel() {
    int n = blockIdx.x * blockDim.x + threadIdx.x;
    if (n < N_NODES) { g_dinv[n] = 0.f; g_cnt[n] = 0; }
}

// Stage 1: deg[src] += w ; cnt[dst] += 1        (edge_index is int32)
__global__ void deg_kernel(const int* __restrict__ ei,
                           const float* __restrict__ ew) {
    int e = blockIdx.x * blockDim.x + threadIdx.x;
    if (e < N_EDGES) {
        atomicAdd(&g_dinv[ei[e]], ew[e]);
        atomicAdd(&g_cnt[ei[N_EDGES + e]], 1);
    }
}

// Stage 2: dinv = deg > 0 ? rsqrt(deg) : 0
__global__ void dinv_kernel() {
    int n = blockIdx.x * blockDim.x + threadIdx.x;
    if (n < N_NODES) {
        float d = g_dinv[n];
        g_dinv[n] = (d > 0.f) ? rsqrtf(d) : 0.f;
    }
}

// Stage 3: norm[e] = -dinv[src] * w[e] * dinv[dst]
__global__ void norm_kernel(const int* __restrict__ ei,
                            const float* __restrict__ ew) {
    int e = blockIdx.x * blockDim.x + threadIdx.x;
    if (e < N_EDGES) {
        int s = ei[e];
        int d = ei[N_EDGES + e];
        g_norm[e] = -g_dinv[s] * ew[e] * g_dinv[d];
    }
}

// ---------------------------------------------------------------------------
// Stage 4: brute-force exclusive scan of g_cnt -> g_rowptr (+ cursor copy)
// ---------------------------------------------------------------------------
#define SCAN_THREADS 1024
#define SCAN_CHUNK   ((N_NODES + SCAN_THREADS - 1) / SCAN_THREADS)   // 49

__global__ void scan_kernel() {
    __shared__ int psum[SCAN_THREADS];
    const int tid = threadIdx.x;
    const int lo  = tid * SCAN_CHUNK;
    const int hi  = min(lo + SCAN_CHUNK, N_NODES);

    int s = 0;
    for (int i = lo; i < hi; i++) s += g_cnt[i];
    psum[tid] = s;
    __syncthreads();

    if (tid == 0) {
        int running = 0;
        for (int i = 0; i < SCAN_THREADS; i++) {
            int t = psum[i];
            psum[i] = running;
            running += t;
        }
    }
    __syncthreads();

    int base = psum[tid];
    for (int i = lo; i < hi; i++) {
        g_rowptr[i] = base;
        g_cursor[i] = base;
        base += g_cnt[i];
    }
}

// Stage 5: scatter packed (src, norm) into dst-grouped CSR slots
__global__ void scatter_kernel(const int* __restrict__ ei) {
    int e = blockIdx.x * blockDim.x + threadIdx.x;
    if (e < N_EDGES) {
        int s = ei[e];
        int d = ei[N_EDGES + e];
        int pos = atomicAdd(&g_cursor[d], 1);
        g_edges[pos] = make_int2(s, __float_as_int(g_norm[e]));
    }
}

// ---------------------------------------------------------------------------
// Stage 6/7: gather-side propagation, one warp per dst node.
// Device globals referenced DIRECTLY in device code (never via host args —
// on GB300/ATS a host-shadow pointer silently "works" and reads the wrong
// memory; that was the round-5/6 bug).
// ---------------------------------------------------------------------------
__global__ void prop1_csr_kernel(const float* __restrict__ x) {
    int node = (blockIdx.x * blockDim.x + threadIdx.x) >> 5;
    int lane = threadIdx.x & 31;
    if (node >= N_NODES) return;
    int base = g_rowptr[node];
    int cnt  = g_cnt[node];

    float4 acc = make_float4(0.f, 0.f, 0.f, 0.f);
    for (int j = 0; j < cnt; j++) {
        int2 e0 = g_edges[base + j];
        float w0 = __int_as_float(e0.y);
        float4 v0 = ((const float4*)(x + (size_t)e0.x * FDIM))[lane];
        acc.x += w0 * v0.x; acc.y += w0 * v0.y;
        acc.z += w0 * v0.z; acc.w += w0 * v0.w;
    }
    ((float4*)(g_T1 + (size_t)node * FDIM))[lane] = acc;
}

__global__ void prop2_csr_kernel(const float* __restrict__ x) {
    int node = (blockIdx.x * blockDim.x + threadIdx.x) >> 5;
    int lane = threadIdx.x & 31;
    if (node >= N_NODES) return;
    int base = g_rowptr[node];
    int cnt  = g_cnt[node];

    float4 acc = make_float4(0.f, 0.f, 0.f, 0.f);
    for (int j = 0; j < cnt; j++) {
        int2 e0 = g_edges[base + j];
        float w0 = __int_as_float(e0.y);
        float4 v0 = ((const float4*)(g_T1 + (size_t)e0.x * FDIM))[lane];
        acc.x += w0 * v0.x; acc.y += w0 * v0.y;
        acc.z += w0 * v0.z; acc.w += w0 * v0.w;
    }
    float4 xx = ((const float4*)(x + (size_t)node * FDIM))[lane];
    acc.x = 2.f * acc.x - xx.x;
    acc.y = 2.f * acc.y - xx.y;
    acc.z = 2.f * acc.z - xx.z;
    acc.w = 2.f * acc.w - xx.w;
    ((float4*)(g_T2 + (size_t)node * FDIM))[lane] = acc;
}

// ---------------------------------------------------------------------------
// Stage 8: fused GEMM + gate epilogue + output projection (round-4 proven)
// ---------------------------------------------------------------------------
#define BM  64
#define BK  32
#define NKB 12
#define STAGE_FLOATS (BM*BK + BK*256)   // 10240

extern __shared__ float smem[];

__device__ __forceinline__ void cp_async16(uint32_t saddr, const float* g, int bytes) {
    asm volatile("cp.async.cg.shared.global [%0], [%1], 16, %2;"
                 :: "r"(saddr), "l"(g), "r"(bytes) : "memory");
}

__global__ __launch_bounds__(256, 2) void fused_kernel(
    const float* __restrict__ x,
    const float* __restrict__ Wz, const float* __restrict__ Wh,
    const float* __restrict__ bz0, const float* __restrict__ bz1,
    const float* __restrict__ bh0, const float* __restrict__ bh1,
    const float* __restrict__ Wlin, const float* __restrict__ blin,
    float* __restrict__ out)
{
    const int tid = threadIdx.x;
    const int tx  = tid & 15;
    const int ty  = tid >> 4;
    const int m0  = blockIdx.x * BM;

    const uint32_t smem_u32 = (uint32_t)__cvta_generic_to_shared(smem);

    float cz[4][8];
    float ch[4][8];
#pragma unroll
    for (int r = 0; r < 4; r++)
#pragma unroll
        for (int i = 0; i < 8; i++) { cz[r][i] = 0.f; ch[r][i] = 0.f; }

    auto load_stage = [&](int kb, int s) {
        const int col = kb * BK;
        const float* Asrc;
        int c0;
        if (col < 128)      { Asrc = x;    c0 = col; }
        else if (col < 256) { Asrc = g_T1; c0 = col - 128; }
        else                { Asrc = g_T2; c0 = col - 256; }

        uint32_t sa = smem_u32 + (uint32_t)(s * STAGE_FLOATS) * 4u;
        uint32_t sb = sa + BM * BK * 4u;

#pragma unroll
        for (int j = 0; j < 2; j++) {
            int idx = tid + j * 256;
            int m = idx >> 3;
            int c = idx & 7;
            int node  = m0 + m;
            int bytes = (node < N_NODES) ? 16 : 0;
            int nd    = (node < N_NODES) ? node : 0;
            cp_async16(sa + (uint32_t)(m * BK + c * 4) * 4u,
                       Asrc + (size_t)nd * FDIM + c0 + c * 4, bytes);
        }
#pragma unroll
        for (int j = 0; j < 8; j++) {
            int idx  = tid + j * 256;
            int jr   = idx >> 6;
            int col4 = (idx & 63) * 4;
            const float* src = (col4 < 128)
                ? (Wz + (size_t)(col + jr) * 128 + col4)
                : (Wh + (size_t)(col + jr) * 128 + (col4 - 128));
            cp_async16(sb + (uint32_t)(jr * 256 + col4) * 4u, src, 16);
        }
        asm volatile("cp.async.commit_group;" ::: "memory");
    };

    load_stage(0, 0);

    for (int kb = 0; kb < NKB; kb++) {
        int s = kb & 1;
        if (kb + 1 < NKB) {
            load_stage(kb + 1, s ^ 1);
            asm volatile("cp.async.wait_group 1;" ::: "memory");
        } else {
            asm volatile("cp.async.wait_group 0;" ::: "memory");
        }
        __syncthreads();

        const float* A = smem + s * STAGE_FLOATS;
        const float* B = A + BM * BK;

#pragma unroll
        for (int k = 0; k < BK; k++) {
            float a[4];
#pragma unroll
            for (int r = 0; r < 4; r++) a[r] = A[(ty * 4 + r) * BK + k];

            float4 z0 = *(const float4*)(B + k * 256 + tx * 8);
            float4 z1 = *(const float4*)(B + k * 256 + tx * 8 + 4);
            float4 h0 = *(const float4*)(B + k * 256 + 128 + tx * 8);
            float4 h1 = *(const float4*)(B + k * 256 + 128 + tx * 8 + 4);
            float bz[8] = {z0.x, z0.y, z0.z, z0.w, z1.x, z1.y, z1.z, z1.w};
            float bh[8] = {h0.x, h0.y, h0.z, h0.w, h1.x, h1.y, h1.z, h1.w};
#pragma unroll
            for (int r = 0; r < 4; r++) {
#pragma unroll
                for (int i = 0; i < 8; i++) {
                    cz[r][i] += a[r] * bz[i];
                    ch[r][i] += a[r] * bh[i];
                }
            }
        }
        __syncthreads();
    }

    // ---- gate epilogue: Hn into smem ----
    float* Hs = smem;            // [BM][130]
#pragma unroll
    for (int i = 0; i < 8; i++) {
        int h = tx * 8 + i;
        float bzs = bz0[h] + bz1[h];
        float bhs = bh0[h] + bh1[h];
#pragma unroll
        for (int r = 0; r < 4; r++) {
            int m = ty * 4 + r;
            float z  = cz[r][i] + bzs;
            float hp = ch[r][i] + bhs;
            float sig = 1.f / (1.f + __expf(-z));
            Hs[m * 130 + h] = (1.f - sig) * tanhf(hp);
        }
    }
    __syncthreads();

    // ---- output projection ----
    for (int idx = tid; idx < BM * TDIM; idx += 256) {
        int m = idx / TDIM;
        int t = idx % TDIM;
        int node = m0 + m;
        if (node < N_NODES) {
            float acc = blin[t];
            const float* hrow = Hs + m * 130;
#pragma unroll 16
            for (int h = 0; h < HDIM; h++)
                acc += hrow[h] * Wlin[h * TDIM + t];
            out[(size_t)node * TDIM + t] = acc;
        }
    }
}

// ---------------------------------------------------------------------------
// Launch
// ---------------------------------------------------------------------------
extern "C" void kernel_launch(void* const* d_in, const int* in_sizes, int n_in,
                              void* d_out, int out_size) {
    const float* x    = (const float*)d_in[0];
    const int*   ei   = (const int*)d_in[1];      // int32 (JAX x64 disabled)
    const float* ew   = (const float*)d_in[2];
    const float* Wxz  = (const float*)d_in[3];
    const float* bxz  = (const float*)d_in[4];
    const float* bhz  = (const float*)d_in[6];
    const float* Wxh  = (const float*)d_in[11];
    const float* bxh  = (const float*)d_in[12];
    const float* bhh  = (const float*)d_in[14];
    const float* Wlin = (const float*)d_in[15];
    const float* blin = (const float*)d_in[16];
    float*       out  = (float*)d_out;

    const int smem_bytes = 2 * STAGE_FLOATS * sizeof(float);
    cudaFuncSetAttribute(fused_kernel,
                         cudaFuncAttributeMaxDynamicSharedMemorySize, smem_bytes);

    // CSR build
    init_kernel<<<(N_NODES + 255) / 256, 256>>>();
    deg_kernel<<<(N_EDGES + 255) / 256, 256>>>(ei, ew);
    dinv_kernel<<<(N_NODES + 255) / 256, 256>>>();
    norm_kernel<<<(N_EDGES + 255) / 256, 256>>>(ei, ew);
    scan_kernel<<<1, SCAN_THREADS>>>();
    scatter_kernel<<<(N_EDGES + 255) / 256, 256>>>(ei);

    // Gather-side propagation: one warp per node
    const int PROP_BLOCKS = (N_NODES * 32 + 255) / 256;
    prop1_csr_kernel<<<PROP_BLOCKS, 256>>>(x);
    prop2_csr_kernel<<<PROP_BLOCKS, 256>>>(x);

    fused_kernel<<<(N_NODES + BM - 1) / BM, 256, smem_bytes>>>(
        x, Wxz, Wxh, bxz, bhz, bxh, bhh, Wlin, blin, out);
}